// round 3
// baseline (speedup 1.0000x reference)
#include <cuda_runtime.h>
#include <cstdint>

#define NN 100000
#define EE 1600000
#define D 128

// Scratch (static __device__ arrays — allocation is forbidden). 16B-aligned.
__device__ int   g_is64;                              // 1 if edge_index is int64
__device__ __align__(16) float g_deg[NN];
__device__ __align__(16) float g_dinv[NN];
__device__ __align__(16) float g_h[(size_t)NN * D];   // dinv-scaled X@W
__device__ __align__(16) float g_agg[(size_t)NN * D]; // aggregation buffer
__device__ __align__(16) float g_x2[(size_t)NN * D];  // layer-1 output

// ---------------------------------------------------------------------------
// Detect whether the edge buffer is int64 or int32.
// If int64 (values < 2^31), every odd int32 word of the first 32 entries is 0.
// ---------------------------------------------------------------------------
__global__ void detect_kernel(const int* __restrict__ ei32) {
    if (threadIdx.x == 0) {
        int ored = 0;
        #pragma unroll
        for (int i = 0; i < 32; i++) ored |= ei32[2 * i + 1];
        g_is64 = (ored == 0) ? 1 : 0;
    }
}

__device__ __forceinline__ int load_idx(const int* __restrict__ ei32,
                                        long long pos, int is64) {
    int v = is64 ? ei32[2 * pos] : ei32[pos];   // little-endian low word
    return min(max(v, 0), NN - 1);              // clamp: never trap
}

// ---------------------------------------------------------------------------
// Degree / normalization  (deg counted on dst, +1 self-loop)
// ---------------------------------------------------------------------------
__global__ void init_deg_kernel() {
    int i = blockIdx.x * blockDim.x + threadIdx.x;
    if (i < NN) g_deg[i] = 1.0f;
}

__global__ void count_deg_kernel(const int* __restrict__ ei32) {
    int e = blockIdx.x * blockDim.x + threadIdx.x;
    if (e >= EE) return;
    int is64 = g_is64;
    int d = load_idx(ei32, (long long)EE + e, is64);  // dst = second half
    atomicAdd(&g_deg[d], 1.0f);
}

__global__ void dinv_kernel() {
    int i = blockIdx.x * blockDim.x + threadIdx.x;
    if (i < NN) g_dinv[i] = rsqrtf(g_deg[i]);
}

// ---------------------------------------------------------------------------
// GEMM with scaled epilogue: H[i,:] = dinv[i]*(X[i,:]@W); AGG = H (self-loop).
// 128x128 tile per block, 256 threads, 4x16 per thread. Static smem 34 KB.
// X == nullptr means "read layer-1 output g_x2".
// ---------------------------------------------------------------------------
__global__ void __launch_bounds__(256)
gemm_scaled_kernel(const float* __restrict__ X, const float* __restrict__ W) {
    __shared__ float sW[32 * 128];   // W rows k0..k0+31
    __shared__ float sX[128 * 36];   // X tile, padded stride 36 (16B-aligned)

    const float* Xp = X ? X : (const float*)g_x2;

    int tid = threadIdx.x;
    int row0 = blockIdx.x * 128;
    int tr = tid >> 3;   // 0..31
    int tc = tid & 7;    // 0..7

    float acc[4][16];
    #pragma unroll
    for (int i = 0; i < 4; i++)
        #pragma unroll
        for (int j = 0; j < 16; j++) acc[i][j] = 0.0f;

    for (int k0 = 0; k0 < 128; k0 += 32) {
        __syncthreads();
        // Load W chunk: rows k0..k0+31, 128 cols = 1024 float4
        #pragma unroll
        for (int it = 0; it < 4; it++) {
            int f = tid + it * 256;          // float4 slot 0..1023
            int r = f >> 5;                  // 0..31 (32 float4 per row)
            int c = f & 31;
            ((float4*)sW)[f] =
                *(const float4*)(W + (size_t)(k0 + r) * 128 + c * 4);
        }
        // Load X tile: 128 rows x 32 k-values (8 float4 per row)
        #pragma unroll
        for (int it = 0; it < 4; it++) {
            int f = tid + it * 256;          // 0..1023
            int row = f >> 3;
            int part = f & 7;
            int gr = row0 + row;
            float4 v = make_float4(0.f, 0.f, 0.f, 0.f);
            if (gr < NN) v = *(const float4*)(Xp + (size_t)gr * D + k0 + part * 4);
            *(float4*)(&sX[row * 36 + part * 4]) = v;
        }
        __syncthreads();

        #pragma unroll
        for (int kk = 0; kk < 32; kk++) {
            float xv[4];
            #pragma unroll
            for (int i = 0; i < 4; i++) xv[i] = sX[(tr + 32 * i) * 36 + kk];
            const float* wr = sW + kk * 128 + tc * 4;
            #pragma unroll
            for (int j = 0; j < 4; j++) {
                float4 w = *(const float4*)(wr + 32 * j);
                #pragma unroll
                for (int i = 0; i < 4; i++) {
                    acc[i][j * 4 + 0] += xv[i] * w.x;
                    acc[i][j * 4 + 1] += xv[i] * w.y;
                    acc[i][j * 4 + 2] += xv[i] * w.z;
                    acc[i][j * 4 + 3] += xv[i] * w.w;
                }
            }
        }
    }

    // Epilogue: scale by dinv, write H and AGG (self-loop init)
    #pragma unroll
    for (int i = 0; i < 4; i++) {
        int gr = row0 + tr + 32 * i;
        if (gr >= NN) continue;
        float sc = g_dinv[gr];
        #pragma unroll
        for (int j = 0; j < 4; j++) {
            float4 v;
            v.x = acc[i][j * 4 + 0] * sc;
            v.y = acc[i][j * 4 + 1] * sc;
            v.z = acc[i][j * 4 + 2] * sc;
            v.w = acc[i][j * 4 + 3] * sc;
            size_t off = (size_t)gr * D + tc * 4 + 32 * j;
            *(float4*)(g_h + off) = v;
            *(float4*)(g_agg + off) = v;
        }
    }
}

// ---------------------------------------------------------------------------
// Edge scatter: one warp per edge; agg[dst] += h[src].
// ---------------------------------------------------------------------------
__global__ void scatter_kernel(const int* __restrict__ ei32) {
    int w = (blockIdx.x * blockDim.x + threadIdx.x) >> 5;
    int lane = threadIdx.x & 31;
    if (w >= EE) return;
    int is64 = g_is64;
    int s = load_idx(ei32, w, is64);
    int d = load_idx(ei32, (long long)EE + w, is64);
    float4 v = *(const float4*)(g_h + (size_t)s * D + lane * 4);
    float* ap = g_agg + (size_t)d * D + lane * 4;
    atomicAdd(ap + 0, v.x);
    atomicAdd(ap + 1, v.y);
    atomicAdd(ap + 2, v.z);
    atomicAdd(ap + 3, v.w);
}

// ---------------------------------------------------------------------------
// Finalize: out = [relu](dinv[i]*agg[i,:] + b).  out==nullptr -> g_x2.
// ---------------------------------------------------------------------------
__global__ void finalize_kernel(const float* __restrict__ b,
                                float* __restrict__ out, int do_relu) {
    int t = blockIdx.x * blockDim.x + threadIdx.x;
    int node = t >> 5;
    if (node >= NN) return;
    float* o = out ? out : (float*)g_x2;
    int c4 = (t & 31) * 4;
    float sc = g_dinv[node];
    float4 a = *(const float4*)(g_agg + (size_t)node * D + c4);
    float4 bb = *(const float4*)(b + c4);
    float4 r;
    r.x = a.x * sc + bb.x;
    r.y = a.y * sc + bb.y;
    r.z = a.z * sc + bb.z;
    r.w = a.w * sc + bb.w;
    if (do_relu) {
        r.x = fmaxf(r.x, 0.f); r.y = fmaxf(r.y, 0.f);
        r.z = fmaxf(r.z, 0.f); r.w = fmaxf(r.w, 0.f);
    }
    *(float4*)(o + (size_t)node * D + c4) = r;
}

// ---------------------------------------------------------------------------
// Launch — kernel launches ONLY (graph-capture safe, no runtime API calls)
// ---------------------------------------------------------------------------
extern "C" void kernel_launch(void* const* d_in, const int* in_sizes, int n_in,
                              void* d_out, int out_size) {
    const float* x   = (const float*)d_in[0];
    const int*   ei  = (const int*)d_in[1];   // width auto-detected on device
    const float* W1  = (const float*)d_in[2];
    const float* b1  = (const float*)d_in[3];
    const float* W2  = (const float*)d_in[4];
    const float* b2  = (const float*)d_in[5];
    float* out = (float*)d_out;

    const int T = 256;
    const int nb_n    = (NN + T - 1) / T;
    const int nb_e    = (EE + T - 1) / T;
    const int nb_gemm = (NN + 127) / 128;
    const int nb_scat = (EE + 7) / 8;        // 8 warps/block, 1 edge/warp
    const int nb_fin  = (NN * 32 + T - 1) / T;

    detect_kernel<<<1, 32>>>(ei);
    init_deg_kernel<<<nb_n, T>>>();
    count_deg_kernel<<<nb_e, T>>>(ei);
    dinv_kernel<<<nb_n, T>>>();

    // Layer 1
    gemm_scaled_kernel<<<nb_gemm, T>>>(x, W1);
    scatter_kernel<<<nb_scat, T>>>(ei);
    finalize_kernel<<<nb_fin, T>>>(b1, nullptr, 1);

    // Layer 2
    gemm_scaled_kernel<<<nb_gemm, T>>>(nullptr, W2);
    scatter_kernel<<<nb_scat, T>>>(ei);
    finalize_kernel<<<nb_fin, T>>>(b2, out, 0);
}

// round 4
// speedup vs baseline: 3.1625x; 3.1625x over previous
#include <cuda_runtime.h>
#include <cstdint>

#define NN 100000
#define EE 1600000
#define D 128

#define SCAN_CHUNK 1024
#define SCAN_NBLK ((NN + SCAN_CHUNK - 1) / SCAN_CHUNK)   // 98

// Scratch (static __device__ arrays — allocation is forbidden). 16B-aligned.
__device__ int g_is64;
__device__ __align__(16) int   g_src[EE];
__device__ __align__(16) int   g_dst[EE];
__device__ __align__(16) int   g_cnt[NN];        // per-node in-degree (edges only)
__device__ __align__(16) int   g_rowptr[NN + 1]; // CSR offsets (exclusive scan)
__device__ __align__(16) int   g_cursor[NN];     // fill cursors
__device__ __align__(16) int   g_col[EE];        // src ids sorted by dst
__device__ __align__(16) int   g_part[SCAN_NBLK];
__device__ __align__(16) float g_dinv[NN];
__device__ __align__(16) float g_h[(size_t)NN * D];   // dinv-scaled X@W
__device__ __align__(16) float g_x2[(size_t)NN * D];  // layer-1 output

// ---------------------------------------------------------------------------
// Edge-width detection (int64 vs int32 delivery)
// ---------------------------------------------------------------------------
__global__ void detect_kernel(const int* __restrict__ ei32) {
    if (threadIdx.x == 0) {
        int ored = 0;
        #pragma unroll
        for (int i = 0; i < 32; i++) ored |= ei32[2 * i + 1];
        g_is64 = (ored == 0) ? 1 : 0;
    }
}

// Zero counts
__global__ void zero_cnt_kernel() {
    int i = blockIdx.x * blockDim.x + threadIdx.x;
    if (i < NN) g_cnt[i] = 0;
}

// Decode edges to int32 src/dst (clamped) + histogram dst
__global__ void convert_hist_kernel(const int* __restrict__ ei32) {
    int e = blockIdx.x * blockDim.x + threadIdx.x;
    if (e >= EE) return;
    int is64 = g_is64;
    int s = is64 ? ei32[2 * (long long)e] : ei32[e];
    int d = is64 ? ei32[2 * ((long long)EE + e)] : ei32[EE + e];
    s = min(max(s, 0), NN - 1);
    d = min(max(d, 0), NN - 1);
    g_src[e] = s;
    g_dst[e] = d;
    atomicAdd(&g_cnt[d], 1);
}

// ---------------------------------------------------------------------------
// Exclusive scan of g_cnt -> g_rowptr (3-kernel hierarchical scan)
// ---------------------------------------------------------------------------
__global__ void scan1_kernel() {   // grid=SCAN_NBLK, block=1024
    __shared__ int sh[SCAN_CHUNK];
    int i = blockIdx.x * SCAN_CHUNK + threadIdx.x;
    int v = (i < NN) ? g_cnt[i] : 0;
    sh[threadIdx.x] = v;
    __syncthreads();
    // Hillis-Steele inclusive scan
    #pragma unroll
    for (int off = 1; off < SCAN_CHUNK; off <<= 1) {
        int t = (threadIdx.x >= off) ? sh[threadIdx.x - off] : 0;
        __syncthreads();
        sh[threadIdx.x] += t;
        __syncthreads();
    }
    if (i <= NN - 1) g_rowptr[i] = sh[threadIdx.x] - v;  // exclusive (no offset yet)
    if (threadIdx.x == SCAN_CHUNK - 1) g_part[blockIdx.x] = sh[threadIdx.x];
}

__global__ void scan2_kernel() {   // 1 block, 1 thread: scan 98 partials
    if (threadIdx.x == 0) {
        int run = 0;
        for (int b = 0; b < SCAN_NBLK; b++) {
            int t = g_part[b];
            g_part[b] = run;
            run += t;
        }
        g_rowptr[NN] = run;   // == EE
    }
}

__global__ void scan3_kernel() {   // add block offsets; init cursors
    int i = blockIdx.x * blockDim.x + threadIdx.x;
    if (i >= NN) return;
    int rp = g_rowptr[i] + g_part[i / SCAN_CHUNK];
    g_rowptr[i] = rp;
    g_cursor[i] = rp;
}

// dinv from CSR degree (+1 self-loop)
__global__ void dinv_kernel() {
    int i = blockIdx.x * blockDim.x + threadIdx.x;
    if (i < NN) {
        int deg = g_rowptr[i + 1] - g_rowptr[i] + 1;
        g_dinv[i] = rsqrtf((float)deg);
    }
}

// Fill CSR column array (src ids grouped by dst)
__global__ void fill_kernel() {
    int e = blockIdx.x * blockDim.x + threadIdx.x;
    if (e >= EE) return;
    int d = g_dst[e];
    int pos = atomicAdd(&g_cursor[d], 1);
    g_col[pos] = g_src[e];
}

// ---------------------------------------------------------------------------
// GEMM with scaled epilogue: H[i,:] = dinv[i]*(X[i,:]@W).
// 128x128 tile per block, 256 threads, 4x16 per thread. Static smem 34 KB.
// X == nullptr -> read g_x2 (layer-1 output).
// ---------------------------------------------------------------------------
__global__ void __launch_bounds__(256)
gemm_scaled_kernel(const float* __restrict__ X, const float* __restrict__ W) {
    __shared__ float sW[32 * 128];
    __shared__ float sX[128 * 36];

    const float* Xp = X ? X : (const float*)g_x2;

    int tid = threadIdx.x;
    int row0 = blockIdx.x * 128;
    int tr = tid >> 3;
    int tc = tid & 7;

    float acc[4][16];
    #pragma unroll
    for (int i = 0; i < 4; i++)
        #pragma unroll
        for (int j = 0; j < 16; j++) acc[i][j] = 0.0f;

    for (int k0 = 0; k0 < 128; k0 += 32) {
        __syncthreads();
        #pragma unroll
        for (int it = 0; it < 4; it++) {
            int f = tid + it * 256;
            int r = f >> 5;
            int c = f & 31;
            ((float4*)sW)[f] = *(const float4*)(W + (size_t)(k0 + r) * 128 + c * 4);
        }
        #pragma unroll
        for (int it = 0; it < 4; it++) {
            int f = tid + it * 256;
            int row = f >> 3;
            int part = f & 7;
            int gr = row0 + row;
            float4 v = make_float4(0.f, 0.f, 0.f, 0.f);
            if (gr < NN) v = *(const float4*)(Xp + (size_t)gr * D + k0 + part * 4);
            *(float4*)(&sX[row * 36 + part * 4]) = v;
        }
        __syncthreads();

        #pragma unroll
        for (int kk = 0; kk < 32; kk++) {
            float xv[4];
            #pragma unroll
            for (int i = 0; i < 4; i++) xv[i] = sX[(tr + 32 * i) * 36 + kk];
            const float* wr = sW + kk * 128 + tc * 4;
            #pragma unroll
            for (int j = 0; j < 4; j++) {
                float4 w = *(const float4*)(wr + 32 * j);
                #pragma unroll
                for (int i = 0; i < 4; i++) {
                    acc[i][j * 4 + 0] += xv[i] * w.x;
                    acc[i][j * 4 + 1] += xv[i] * w.y;
                    acc[i][j * 4 + 2] += xv[i] * w.z;
                    acc[i][j * 4 + 3] += xv[i] * w.w;
                }
            }
        }
    }

    #pragma unroll
    for (int i = 0; i < 4; i++) {
        int gr = row0 + tr + 32 * i;
        if (gr >= NN) continue;
        float sc = g_dinv[gr];
        #pragma unroll
        for (int j = 0; j < 4; j++) {
            float4 v;
            v.x = acc[i][j * 4 + 0] * sc;
            v.y = acc[i][j * 4 + 1] * sc;
            v.z = acc[i][j * 4 + 2] * sc;
            v.w = acc[i][j * 4 + 3] * sc;
            *(float4*)(g_h + (size_t)gr * D + tc * 4 + 32 * j) = v;
        }
    }
}

// ---------------------------------------------------------------------------
// Atomic-free aggregation: warp per node.
// acc = h[node] (self-loop) + sum over incoming edges h[src];
// out = [relu](acc * dinv[node] + b). Fuses old scatter+finalize.
// ---------------------------------------------------------------------------
__global__ void __launch_bounds__(256)
gather_kernel(const float* __restrict__ b, float* __restrict__ out, int do_relu) {
    int warp = (blockIdx.x * blockDim.x + threadIdx.x) >> 5;
    int lane = threadIdx.x & 31;
    if (warp >= NN) return;
    int node = warp;

    int beg = g_rowptr[node];
    int end = g_rowptr[node + 1];

    // self-loop contribution (h already carries dinv[node])
    float4 acc = *(const float4*)(g_h + (size_t)node * D + lane * 4);

    for (int j = beg; j < end; j += 32) {
        int e = j + lane;
        int c = (e < end) ? g_col[e] : 0;
        int m = min(32, end - j);
        for (int t = 0; t < m; t++) {
            int s = __shfl_sync(0xffffffffu, c, t);
            float4 v = *(const float4*)(g_h + (size_t)s * D + lane * 4);
            acc.x += v.x; acc.y += v.y; acc.z += v.z; acc.w += v.w;
        }
    }

    float sc = g_dinv[node];
    float4 bb = *(const float4*)(b + lane * 4);
    float4 r;
    r.x = acc.x * sc + bb.x;
    r.y = acc.y * sc + bb.y;
    r.z = acc.z * sc + bb.z;
    r.w = acc.w * sc + bb.w;
    if (do_relu) {
        r.x = fmaxf(r.x, 0.f); r.y = fmaxf(r.y, 0.f);
        r.z = fmaxf(r.z, 0.f); r.w = fmaxf(r.w, 0.f);
    }
    float* o = out ? out : (float*)g_x2;
    *(float4*)(o + (size_t)node * D + lane * 4) = r;
}

// ---------------------------------------------------------------------------
// Launch — kernel launches only (graph-capture safe)
// ---------------------------------------------------------------------------
extern "C" void kernel_launch(void* const* d_in, const int* in_sizes, int n_in,
                              void* d_out, int out_size) {
    const float* x  = (const float*)d_in[0];
    const int*   ei = (const int*)d_in[1];
    const float* W1 = (const float*)d_in[2];
    const float* b1 = (const float*)d_in[3];
    const float* W2 = (const float*)d_in[4];
    const float* b2 = (const float*)d_in[5];
    float* out = (float*)d_out;

    const int T = 256;
    const int nb_n    = (NN + T - 1) / T;
    const int nb_e    = (EE + T - 1) / T;
    const int nb_gemm = (NN + 127) / 128;
    const int nb_gath = (NN * 32 + T - 1) / T;   // warp per node

    // Graph preprocessing (shared by both layers)
    detect_kernel<<<1, 32>>>(ei);
    zero_cnt_kernel<<<nb_n, T>>>();
    convert_hist_kernel<<<nb_e, T>>>(ei);
    scan1_kernel<<<SCAN_NBLK, SCAN_CHUNK>>>();
    scan2_kernel<<<1, 32>>>();
    scan3_kernel<<<nb_n, T>>>();
    dinv_kernel<<<nb_n, T>>>();
    fill_kernel<<<nb_e, T>>>();

    // Layer 1
    gemm_scaled_kernel<<<nb_gemm, T>>>(x, W1);
    gather_kernel<<<nb_gath, T>>>(b1, nullptr, 1);

    // Layer 2
    gemm_scaled_kernel<<<nb_gemm, T>>>(nullptr, W2);
    gather_kernel<<<nb_gath, T>>>(b2, out, 0);
}

// round 5
// speedup vs baseline: 3.4656x; 1.0958x over previous
#include <cuda_runtime.h>
#include <cstdint>

#define NN 100000
#define EE 1600000
#define D 128

#define SCAN_CHUNK 1024
#define SCAN_NBLK ((NN + SCAN_CHUNK - 1) / SCAN_CHUNK)   // 98

// Packed fp32x2 helpers (Blackwell FFMA2 path)
#define PACK_F32X2(out, lo, hi) \
    asm("mov.b64 %0, {%1, %2};" : "=l"(out) : "r"(lo), "r"(hi))
#define UNPACK_F32X2(lo, hi, in) \
    asm("mov.b64 {%0, %1}, %2;" : "=r"(lo), "=r"(hi) : "l"(in))
#define FMA_F32X2(d, a, b) \
    asm("fma.rn.f32x2 %0, %1, %2, %0;" : "+l"(d) : "l"(a), "l"(b))

// Scratch (static __device__ arrays — allocation is forbidden). 16B-aligned.
__device__ int g_is64;
__device__ __align__(16) int   g_src[EE];
__device__ __align__(16) int   g_dst[EE];
__device__ __align__(16) int   g_cnt[NN];
__device__ __align__(16) int   g_rowptr[NN + 1];
__device__ __align__(16) int   g_cursor[NN];
__device__ __align__(16) int   g_col[EE];
__device__ __align__(16) int   g_part[SCAN_NBLK];
__device__ __align__(16) float g_dinv[NN];
__device__ __align__(16) float g_h[(size_t)NN * D];
__device__ __align__(16) float g_x2[(size_t)NN * D];

// ---------------------------------------------------------------------------
// Edge-width detection (int64 vs int32 delivery)
// ---------------------------------------------------------------------------
__global__ void detect_kernel(const int* __restrict__ ei32) {
    if (threadIdx.x == 0) {
        int ored = 0;
        #pragma unroll
        for (int i = 0; i < 32; i++) ored |= ei32[2 * i + 1];
        g_is64 = (ored == 0) ? 1 : 0;
    }
}

__global__ void zero_cnt_kernel() {
    int i = blockIdx.x * blockDim.x + threadIdx.x;
    if (i < NN) g_cnt[i] = 0;
}

__global__ void convert_hist_kernel(const int* __restrict__ ei32) {
    int e = blockIdx.x * blockDim.x + threadIdx.x;
    if (e >= EE) return;
    int is64 = g_is64;
    int s = is64 ? ei32[2 * (long long)e] : ei32[e];
    int d = is64 ? ei32[2 * ((long long)EE + e)] : ei32[EE + e];
    s = min(max(s, 0), NN - 1);
    d = min(max(d, 0), NN - 1);
    g_src[e] = s;
    g_dst[e] = d;
    atomicAdd(&g_cnt[d], 1);
}

// ---------------------------------------------------------------------------
// Hierarchical exclusive scan of g_cnt -> g_rowptr
// ---------------------------------------------------------------------------
__global__ void scan1_kernel() {   // grid=SCAN_NBLK, block=1024
    __shared__ int sh[SCAN_CHUNK];
    int i = blockIdx.x * SCAN_CHUNK + threadIdx.x;
    int v = (i < NN) ? g_cnt[i] : 0;
    sh[threadIdx.x] = v;
    __syncthreads();
    #pragma unroll
    for (int off = 1; off < SCAN_CHUNK; off <<= 1) {
        int t = (threadIdx.x >= off) ? sh[threadIdx.x - off] : 0;
        __syncthreads();
        sh[threadIdx.x] += t;
        __syncthreads();
    }
    if (i <= NN - 1) g_rowptr[i] = sh[threadIdx.x] - v;
    if (threadIdx.x == SCAN_CHUNK - 1) g_part[blockIdx.x] = sh[threadIdx.x];
}

__global__ void scan2_kernel() {   // 1 block, 128 threads: scan 98 partials
    __shared__ int sh[128];
    int t = threadIdx.x;
    int v = (t < SCAN_NBLK) ? g_part[t] : 0;
    sh[t] = v;
    __syncthreads();
    #pragma unroll
    for (int off = 1; off < 128; off <<= 1) {
        int u = (t >= off) ? sh[t - off] : 0;
        __syncthreads();
        sh[t] += u;
        __syncthreads();
    }
    if (t < SCAN_NBLK) g_part[t] = sh[t] - v;       // exclusive
    if (t == 127) g_rowptr[NN] = sh[127];           // == EE
}

__global__ void scan3_kernel() {
    int i = blockIdx.x * blockDim.x + threadIdx.x;
    if (i >= NN) return;
    int rp = g_rowptr[i] + g_part[i / SCAN_CHUNK];
    g_rowptr[i] = rp;
    g_cursor[i] = rp;
}

__global__ void dinv_kernel() {
    int i = blockIdx.x * blockDim.x + threadIdx.x;
    if (i < NN) {
        int deg = g_rowptr[i + 1] - g_rowptr[i] + 1;
        g_dinv[i] = rsqrtf((float)deg);
    }
}

__global__ void fill_kernel() {
    int e = blockIdx.x * blockDim.x + threadIdx.x;
    if (e >= EE) return;
    int d = g_dst[e];
    int pos = atomicAdd(&g_cursor[d], 1);
    g_col[pos] = g_src[e];
}

// ---------------------------------------------------------------------------
// GEMM with scaled epilogue using packed fp32x2 FMA (FFMA2):
// H[i,:] = dinv[i]*(X[i,:]@W). 128x128 tile, 256 threads, 4 rows x 16 cols
// per thread held as 4x8 f32x2 pairs. X == nullptr -> read g_x2.
// ---------------------------------------------------------------------------
__global__ void __launch_bounds__(256)
gemm_scaled_kernel(const float* __restrict__ X, const float* __restrict__ W) {
    __shared__ float sW[32 * 128];
    __shared__ float sX[128 * 36];

    const float* Xp = X ? X : (const float*)g_x2;

    int tid = threadIdx.x;
    int row0 = blockIdx.x * 128;
    int tr = tid >> 3;   // 0..31
    int tc = tid & 7;    // 0..7

    unsigned long long acc2[4][8];   // [row][col-pair]
    #pragma unroll
    for (int i = 0; i < 4; i++)
        #pragma unroll
        for (int j = 0; j < 8; j++) acc2[i][j] = 0ull;

    for (int k0 = 0; k0 < 128; k0 += 32) {
        __syncthreads();
        // W chunk: rows k0..k0+31 x 128 cols = 1024 float4
        #pragma unroll
        for (int it = 0; it < 4; it++) {
            int f = tid + it * 256;
            int r = f >> 5;
            int c = f & 31;
            ((float4*)sW)[f] = *(const float4*)(W + (size_t)(k0 + r) * 128 + c * 4);
        }
        // X tile: 128 rows x 32 k-values
        #pragma unroll
        for (int it = 0; it < 4; it++) {
            int f = tid + it * 256;
            int row = f >> 3;
            int part = f & 7;
            int gr = row0 + row;
            float4 v = make_float4(0.f, 0.f, 0.f, 0.f);
            if (gr < NN) v = *(const float4*)(Xp + (size_t)gr * D + k0 + part * 4);
            *(float4*)(&sX[row * 36 + part * 4]) = v;
        }
        __syncthreads();

        #pragma unroll 16
        for (int kk = 0; kk < 32; kk++) {
            unsigned long long xv2[4];
            #pragma unroll
            for (int i = 0; i < 4; i++) {
                float xv = sX[(tr + 32 * i) * 36 + kk];
                unsigned int xb = __float_as_uint(xv);
                PACK_F32X2(xv2[i], xb, xb);
            }
            const float* wr = sW + kk * 128 + tc * 4;
            #pragma unroll
            for (int j = 0; j < 4; j++) {
                ulonglong2 w2 = *(const ulonglong2*)(wr + 32 * j);
                #pragma unroll
                for (int i = 0; i < 4; i++) {
                    FMA_F32X2(acc2[i][j * 2 + 0], xv2[i], w2.x);
                    FMA_F32X2(acc2[i][j * 2 + 1], xv2[i], w2.y);
                }
            }
        }
    }

    // Epilogue: unpack, scale by dinv, store
    #pragma unroll
    for (int i = 0; i < 4; i++) {
        int gr = row0 + tr + 32 * i;
        if (gr >= NN) continue;
        float sc = g_dinv[gr];
        #pragma unroll
        for (int j = 0; j < 4; j++) {
            unsigned int a0, a1, a2, a3;
            UNPACK_F32X2(a0, a1, acc2[i][j * 2 + 0]);
            UNPACK_F32X2(a2, a3, acc2[i][j * 2 + 1]);
            float4 v;
            v.x = __uint_as_float(a0) * sc;
            v.y = __uint_as_float(a1) * sc;
            v.z = __uint_as_float(a2) * sc;
            v.w = __uint_as_float(a3) * sc;
            *(float4*)(g_h + (size_t)gr * D + tc * 4 + 32 * j) = v;
        }
    }
}

// ---------------------------------------------------------------------------
// Atomic-free aggregation: warp per node, MLP-4 unrolled inner loop.
// acc = h[node] (self-loop) + sum_{src in-edges} h[src];
// out = [relu](acc * dinv[node] + b).
// ---------------------------------------------------------------------------
__global__ void __launch_bounds__(256)
gather_kernel(const float* __restrict__ b, float* __restrict__ out, int do_relu) {
    int warp = (blockIdx.x * blockDim.x + threadIdx.x) >> 5;
    int lane = threadIdx.x & 31;
    if (warp >= NN) return;
    int node = warp;

    int beg = g_rowptr[node];
    int end = g_rowptr[node + 1];

    float4 acc = *(const float4*)(g_h + (size_t)node * D + lane * 4);

    for (int j = beg; j < end; j += 32) {
        int e = j + lane;
        int c = (e < end) ? __ldg(&g_col[e]) : 0;
        int m = min(32, end - j);
        int t = 0;
        for (; t + 4 <= m; t += 4) {
            int s0 = __shfl_sync(0xffffffffu, c, t + 0);
            int s1 = __shfl_sync(0xffffffffu, c, t + 1);
            int s2 = __shfl_sync(0xffffffffu, c, t + 2);
            int s3 = __shfl_sync(0xffffffffu, c, t + 3);
            float4 v0 = *(const float4*)(g_h + (size_t)s0 * D + lane * 4);
            float4 v1 = *(const float4*)(g_h + (size_t)s1 * D + lane * 4);
            float4 v2 = *(const float4*)(g_h + (size_t)s2 * D + lane * 4);
            float4 v3 = *(const float4*)(g_h + (size_t)s3 * D + lane * 4);
            acc.x += v0.x + v1.x + v2.x + v3.x;
            acc.y += v0.y + v1.y + v2.y + v3.y;
            acc.z += v0.z + v1.z + v2.z + v3.z;
            acc.w += v0.w + v1.w + v2.w + v3.w;
        }
        for (; t < m; t++) {
            int s = __shfl_sync(0xffffffffu, c, t);
            float4 v = *(const float4*)(g_h + (size_t)s * D + lane * 4);
            acc.x += v.x; acc.y += v.y; acc.z += v.z; acc.w += v.w;
        }
    }

    float sc = g_dinv[node];
    float4 bb = *(const float4*)(b + lane * 4);
    float4 r;
    r.x = acc.x * sc + bb.x;
    r.y = acc.y * sc + bb.y;
    r.z = acc.z * sc + bb.z;
    r.w = acc.w * sc + bb.w;
    if (do_relu) {
        r.x = fmaxf(r.x, 0.f); r.y = fmaxf(r.y, 0.f);
        r.z = fmaxf(r.z, 0.f); r.w = fmaxf(r.w, 0.f);
    }
    float* o = out ? out : (float*)g_x2;
    *(float4*)(o + (size_t)node * D + lane * 4) = r;
}

// ---------------------------------------------------------------------------
// Launch — kernel launches only (graph-capture safe)
// ---------------------------------------------------------------------------
extern "C" void kernel_launch(void* const* d_in, const int* in_sizes, int n_in,
                              void* d_out, int out_size) {
    const float* x  = (const float*)d_in[0];
    const int*   ei = (const int*)d_in[1];
    const float* W1 = (const float*)d_in[2];
    const float* b1 = (const float*)d_in[3];
    const float* W2 = (const float*)d_in[4];
    const float* b2 = (const float*)d_in[5];
    float* out = (float*)d_out;

    const int T = 256;
    const int nb_n    = (NN + T - 1) / T;
    const int nb_e    = (EE + T - 1) / T;
    const int nb_gemm = (NN + 127) / 128;
    const int nb_gath = (NN * 32 + T - 1) / T;

    // Graph preprocessing (shared by both layers)
    detect_kernel<<<1, 32>>>(ei);
    zero_cnt_kernel<<<nb_n, T>>>();
    convert_hist_kernel<<<nb_e, T>>>(ei);
    scan1_kernel<<<SCAN_NBLK, SCAN_CHUNK>>>();
    scan2_kernel<<<1, 128>>>();
    scan3_kernel<<<nb_n, T>>>();
    dinv_kernel<<<nb_n, T>>>();
    fill_kernel<<<nb_e, T>>>();

    // Layer 1
    gemm_scaled_kernel<<<nb_gemm, T>>>(x, W1);
    gather_kernel<<<nb_gath, T>>>(b1, nullptr, 1);

    // Layer 2
    gemm_scaled_kernel<<<nb_gemm, T>>>(nullptr, W2);
    gather_kernel<<<nb_gath, T>>>(b2, out, 0);
}

// round 7
// speedup vs baseline: 4.3326x; 1.2502x over previous
#include <cuda_runtime.h>
#include <cuda_bf16.h>
#include <cstdint>

#define NN 100000
#define EE 1600000
#define D 128
#define NTILES ((NN + 127) / 128)   // 782

#define SCAN_CHUNK 1024
#define SCAN_NBLK ((NN + SCAN_CHUNK - 1) / SCAN_CHUNK)   // 98

// Padded smem strides (bf16 elements): 272B rows -> conflict-free ldmatrix
#define SA 136
#define SB 136
#define A_BYTES (128 * SA * 2)          // 34816
#define GEMM_DSMEM (4 * A_BYTES)        // A_hi, A_lo, B_hi, B_lo = 139264

// ---------------------------------------------------------------------------
// Scratch (static __device__ arrays — allocation is forbidden)
// ---------------------------------------------------------------------------
__device__ int g_is64;
__device__ __align__(16) int   g_src[EE];
__device__ __align__(16) int   g_dst[EE];
__device__ __align__(16) int   g_cnt[NN];
__device__ __align__(16) int   g_rowptr[NN + 1];
__device__ __align__(16) int   g_cursor[NN];
__device__ __align__(16) int   g_col[EE];
__device__ __align__(16) int   g_part[SCAN_NBLK];
__device__ __align__(16) float g_dinv[NN];
__device__ __align__(16) float g_h[(size_t)NN * D];
__device__ __align__(16) float g_x2[(size_t)NN * D];
// W split: bf16 hi/lo, plain row-major [k][n] (= W layout itself)
__device__ __align__(16) __nv_bfloat16 g_wh[16384];
__device__ __align__(16) __nv_bfloat16 g_wl[16384];

// ---------------------------------------------------------------------------
// PTX helpers
// ---------------------------------------------------------------------------
__device__ __forceinline__ uint32_t smem_u32(const void* p) {
    uint32_t a;
    asm("{ .reg .u64 t; cvta.to.shared.u64 t, %1; cvt.u32.u64 %0, t; }"
        : "=r"(a) : "l"(p));
    return a;
}

__device__ __forceinline__ void ldmatrix_x4(uint32_t* r, uint32_t addr) {
    asm volatile("ldmatrix.sync.aligned.m8n8.x4.shared.b16 {%0,%1,%2,%3}, [%4];"
                 : "=r"(r[0]), "=r"(r[1]), "=r"(r[2]), "=r"(r[3]) : "r"(addr));
}
__device__ __forceinline__ void ldmatrix_x4_t(uint32_t* r, uint32_t addr) {
    asm volatile("ldmatrix.sync.aligned.m8n8.x4.trans.shared.b16 {%0,%1,%2,%3}, [%4];"
                 : "=r"(r[0]), "=r"(r[1]), "=r"(r[2]), "=r"(r[3]) : "r"(addr));
}
__device__ __forceinline__ void mma_bf16(float* c, const uint32_t* a,
                                         const uint32_t* b) {
    asm volatile(
        "mma.sync.aligned.m16n8k16.row.col.f32.bf16.bf16.f32 "
        "{%0,%1,%2,%3}, {%4,%5,%6,%7}, {%8,%9}, {%0,%1,%2,%3};"
        : "+f"(c[0]), "+f"(c[1]), "+f"(c[2]), "+f"(c[3])
        : "r"(a[0]), "r"(a[1]), "r"(a[2]), "r"(a[3]), "r"(b[0]), "r"(b[1]));
}

// ---------------------------------------------------------------------------
// Graph preprocessing
// ---------------------------------------------------------------------------
__global__ void detect_kernel(const int* __restrict__ ei32) {
    if (threadIdx.x == 0) {
        int ored = 0;
        #pragma unroll
        for (int i = 0; i < 32; i++) ored |= ei32[2 * i + 1];
        g_is64 = (ored == 0) ? 1 : 0;
    }
}

__global__ void zero_cnt_kernel() {
    int i = blockIdx.x * blockDim.x + threadIdx.x;
    if (i < NN) g_cnt[i] = 0;
}

__global__ void convert_hist_kernel(const int* __restrict__ ei32) {
    int e = blockIdx.x * blockDim.x + threadIdx.x;
    if (e >= EE) return;
    int is64 = g_is64;
    int s = is64 ? ei32[2 * (long long)e] : ei32[e];
    int d = is64 ? ei32[2 * ((long long)EE + e)] : ei32[EE + e];
    s = min(max(s, 0), NN - 1);
    d = min(max(d, 0), NN - 1);
    g_src[e] = s;
    g_dst[e] = d;
    atomicAdd(&g_cnt[d], 1);
}

__global__ void scan1_kernel() {
    __shared__ int sh[SCAN_CHUNK];
    int i = blockIdx.x * SCAN_CHUNK + threadIdx.x;
    int v = (i < NN) ? g_cnt[i] : 0;
    sh[threadIdx.x] = v;
    __syncthreads();
    #pragma unroll
    for (int off = 1; off < SCAN_CHUNK; off <<= 1) {
        int t = (threadIdx.x >= off) ? sh[threadIdx.x - off] : 0;
        __syncthreads();
        sh[threadIdx.x] += t;
        __syncthreads();
    }
    if (i <= NN - 1) g_rowptr[i] = sh[threadIdx.x] - v;
    if (threadIdx.x == SCAN_CHUNK - 1) g_part[blockIdx.x] = sh[threadIdx.x];
}

__global__ void scan2_kernel() {
    __shared__ int sh[128];
    int t = threadIdx.x;
    int v = (t < SCAN_NBLK) ? g_part[t] : 0;
    sh[t] = v;
    __syncthreads();
    #pragma unroll
    for (int off = 1; off < 128; off <<= 1) {
        int u = (t >= off) ? sh[t - off] : 0;
        __syncthreads();
        sh[t] += u;
        __syncthreads();
    }
    if (t < SCAN_NBLK) g_part[t] = sh[t] - v;
    if (t == 127) g_rowptr[NN] = sh[127];
}

__global__ void scan3_kernel() {   // offsets + cursors + dinv (deg = cnt+1)
    int i = blockIdx.x * blockDim.x + threadIdx.x;
    if (i >= NN) return;
    int rp = g_rowptr[i] + g_part[i / SCAN_CHUNK];
    g_rowptr[i] = rp;
    g_cursor[i] = rp;
    g_dinv[i] = rsqrtf((float)(g_cnt[i] + 1));
}

__global__ void fill_kernel() {
    int e = blockIdx.x * blockDim.x + threadIdx.x;
    if (e >= EE) return;
    int d = g_dst[e];
    int pos = atomicAdd(&g_cursor[d], 1);
    g_col[pos] = g_src[e];
}

// ---------------------------------------------------------------------------
// Prep W: split fp32 W[k][n] into bf16 hi/lo, same row-major layout.
// ---------------------------------------------------------------------------
__global__ void prepw_kernel(const float* __restrict__ W) {
    int e = blockIdx.x * blockDim.x + threadIdx.x;
    if (e >= 16384) return;
    float v = W[e];
    __nv_bfloat16 hi = __float2bfloat16(v);
    __nv_bfloat16 lo = __float2bfloat16(v - __bfloat162float(hi));
    g_wh[e] = hi;
    g_wl[e] = lo;
}

// ---------------------------------------------------------------------------
// mma.sync GEMM: H[m,:] = dinv[m] * (X[m,:] @ W), 128x128 tile per block.
// bf16 error-compensated split: D = Ah@Bh + Al@Bh + Ah@Bl (fp32 accum).
// 512 threads = 16 warps in 4x4 grid; each warp 32 (M) x 32 (N).
// X == nullptr -> read g_x2.
// ---------------------------------------------------------------------------
__global__ void __launch_bounds__(512)
gemm_mma_kernel(const float* __restrict__ X) {
    extern __shared__ char dsm[];
    __nv_bfloat16* sAh = (__nv_bfloat16*)dsm;
    __nv_bfloat16* sAl = (__nv_bfloat16*)(dsm + A_BYTES);
    __nv_bfloat16* sBh = (__nv_bfloat16*)(dsm + 2 * A_BYTES);
    __nv_bfloat16* sBl = (__nv_bfloat16*)(dsm + 3 * A_BYTES);

    const float* Xp = X ? X : (const float*)g_x2;

    int tid = threadIdx.x;
    int wid = tid >> 5;
    int lane = tid & 31;
    int warp_m = wid & 3;     // 4 warps over M (32 rows each)
    int warp_n = wid >> 2;    // 4 warps over N (32 cols each)
    int row0 = blockIdx.x * 128;

    // --- Stage A: fp32 -> bf16 hi/lo, padded row-major ---
    #pragma unroll
    for (int it = 0; it < 8; it++) {
        int f = it * 512 + tid;           // 4096 float4 slots
        int r = f >> 5;
        int p4 = f & 31;
        int gr = row0 + r;
        float4 v = make_float4(0.f, 0.f, 0.f, 0.f);
        if (gr < NN) v = *(const float4*)(Xp + (size_t)gr * D + p4 * 4);

        __nv_bfloat16 h0 = __float2bfloat16(v.x);
        __nv_bfloat16 h1 = __float2bfloat16(v.y);
        __nv_bfloat16 h2 = __float2bfloat16(v.z);
        __nv_bfloat16 h3 = __float2bfloat16(v.w);
        uint2 ph, pl;
        ph.x = ((uint32_t)__bfloat16_as_ushort(h1) << 16) | __bfloat16_as_ushort(h0);
        ph.y = ((uint32_t)__bfloat16_as_ushort(h3) << 16) | __bfloat16_as_ushort(h2);
        __nv_bfloat16 l0 = __float2bfloat16(v.x - __bfloat162float(h0));
        __nv_bfloat16 l1 = __float2bfloat16(v.y - __bfloat162float(h1));
        __nv_bfloat16 l2 = __float2bfloat16(v.z - __bfloat162float(h2));
        __nv_bfloat16 l3 = __float2bfloat16(v.w - __bfloat162float(h3));
        pl.x = ((uint32_t)__bfloat16_as_ushort(l1) << 16) | __bfloat16_as_ushort(l0);
        pl.y = ((uint32_t)__bfloat16_as_ushort(l3) << 16) | __bfloat16_as_ushort(l2);

        int off = r * SA + p4 * 4;        // bf16 elements; 8B-aligned
        *(uint2*)(sAh + off) = ph;
        *(uint2*)(sAl + off) = pl;
    }

    // --- Stage B: copy prepped W hi/lo into padded rows ---
    #pragma unroll
    for (int it = 0; it < 4; it++) {
        int idx = it * 512 + tid;         // 2048 uint4 per array
        int k = idx >> 4;
        int part = idx & 15;
        uint4 vh = ((const uint4*)g_wh)[idx];
        uint4 vl = ((const uint4*)g_wl)[idx];
        int off = k * SB + part * 8;      // 16B-aligned
        *(uint4*)(sBh + off) = vh;
        *(uint4*)(sBl + off) = vl;
    }
    __syncthreads();

    uint32_t baseAh = smem_u32(sAh);
    uint32_t baseAl = baseAh + A_BYTES;
    uint32_t baseBh = baseAh + 2 * A_BYTES;
    uint32_t baseBl = baseAh + 3 * A_BYTES;

    float acc[2][4][4];
    #pragma unroll
    for (int i = 0; i < 2; i++)
        #pragma unroll
        for (int j = 0; j < 4; j++)
            #pragma unroll
            for (int q = 0; q < 4; q++) acc[i][j][q] = 0.0f;

    // A fragment addr: lanes 0-15 -> rows, k0; lanes 16-31 -> rows, k0+8
    int a_row = warp_m * 32 + (lane & 15);
    int a_kadd = (lane >> 4) * 8;
    // B (trans) addr: k-row = k0 + (lane&7) + ((lane>>3)&1)*8; col += (lane>>4)*8
    int b_krow = (lane & 7) + ((lane >> 3) & 1) * 8;
    int b_ncol0 = warp_n * 32 + (lane >> 4) * 8;

    #pragma unroll
    for (int ks = 0; ks < 8; ks++) {
        int k0 = ks * 16;
        uint32_t ah[2][4], al[2][4];
        #pragma unroll
        for (int mt = 0; mt < 2; mt++) {
            uint32_t off = (uint32_t)((a_row + mt * 16) * SA + k0 + a_kadd) * 2;
            ldmatrix_x4(ah[mt], baseAh + off);
            ldmatrix_x4(al[mt], baseAl + off);
        }
        uint32_t bh[4][2], bl[4][2];
        #pragma unroll
        for (int np = 0; np < 2; np++) {   // each x4.trans covers 2 n-tiles
            uint32_t off = (uint32_t)((k0 + b_krow) * SB + b_ncol0 + np * 16) * 2;
            uint32_t t4[4];
            ldmatrix_x4_t(t4, baseBh + off);
            bh[np * 2 + 0][0] = t4[0]; bh[np * 2 + 0][1] = t4[1];
            bh[np * 2 + 1][0] = t4[2]; bh[np * 2 + 1][1] = t4[3];
            ldmatrix_x4_t(t4, baseBl + off);
            bl[np * 2 + 0][0] = t4[0]; bl[np * 2 + 0][1] = t4[1];
            bl[np * 2 + 1][0] = t4[2]; bl[np * 2 + 1][1] = t4[3];
        }
        #pragma unroll
        for (int mt = 0; mt < 2; mt++)
            #pragma unroll
            for (int nt = 0; nt < 4; nt++) {
                mma_bf16(acc[mt][nt], ah[mt], bh[nt]);
                mma_bf16(acc[mt][nt], al[mt], bh[nt]);
                mma_bf16(acc[mt][nt], ah[mt], bl[nt]);
            }
    }

    // --- Epilogue: scale by dinv, store fp32 ---
    #pragma unroll
    for (int mt = 0; mt < 2; mt++) {
        int r_lo = row0 + warp_m * 32 + mt * 16 + (lane >> 2);
        int r_hi = r_lo + 8;
        float dv_lo = (r_lo < NN) ? g_dinv[r_lo] : 0.0f;
        float dv_hi = (r_hi < NN) ? g_dinv[r_hi] : 0.0f;
        #pragma unroll
        for (int nt = 0; nt < 4; nt++) {
            int col = warp_n * 32 + nt * 8 + (lane & 3) * 2;
            if (r_lo < NN) {
                float2 v = make_float2(acc[mt][nt][0] * dv_lo,
                                       acc[mt][nt][1] * dv_lo);
                *(float2*)(g_h + (size_t)r_lo * D + col) = v;
            }
            if (r_hi < NN) {
                float2 v = make_float2(acc[mt][nt][2] * dv_hi,
                                       acc[mt][nt][3] * dv_hi);
                *(float2*)(g_h + (size_t)r_hi * D + col) = v;
            }
        }
    }
}

// ---------------------------------------------------------------------------
// Atomic-free aggregation: warp per node, MLP-4 unrolled.
// out = [relu]((h[node] + sum_{src} h[src]) * dinv[node] + b)
// ---------------------------------------------------------------------------
__global__ void __launch_bounds__(256)
gather_kernel(const float* __restrict__ b, float* __restrict__ out, int do_relu) {
    int warp = (blockIdx.x * blockDim.x + threadIdx.x) >> 5;
    int lane = threadIdx.x & 31;
    if (warp >= NN) return;
    int node = warp;

    int beg = g_rowptr[node];
    int end = g_rowptr[node + 1];

    float4 acc = *(const float4*)(g_h + (size_t)node * D + lane * 4);

    for (int j = beg; j < end; j += 32) {
        int e = j + lane;
        int c = (e < end) ? __ldg(&g_col[e]) : 0;
        int m = min(32, end - j);
        int t = 0;
        for (; t + 4 <= m; t += 4) {
            int s0 = __shfl_sync(0xffffffffu, c, t + 0);
            int s1 = __shfl_sync(0xffffffffu, c, t + 1);
            int s2 = __shfl_sync(0xffffffffu, c, t + 2);
            int s3 = __shfl_sync(0xffffffffu, c, t + 3);
            float4 v0 = *(const float4*)(g_h + (size_t)s0 * D + lane * 4);
            float4 v1 = *(const float4*)(g_h + (size_t)s1 * D + lane * 4);
            float4 v2 = *(const float4*)(g_h + (size_t)s2 * D + lane * 4);
            float4 v3 = *(const float4*)(g_h + (size_t)s3 * D + lane * 4);
            acc.x += v0.x + v1.x + v2.x + v3.x;
            acc.y += v0.y + v1.y + v2.y + v3.y;
            acc.z += v0.z + v1.z + v2.z + v3.z;
            acc.w += v0.w + v1.w + v2.w + v3.w;
        }
        for (; t < m; t++) {
            int s = __shfl_sync(0xffffffffu, c, t);
            float4 v = *(const float4*)(g_h + (size_t)s * D + lane * 4);
            acc.x += v.x; acc.y += v.y; acc.z += v.z; acc.w += v.w;
        }
    }

    float sc = g_dinv[node];
    float4 bb = *(const float4*)(b + lane * 4);
    float4 r;
    r.x = acc.x * sc + bb.x;
    r.y = acc.y * sc + bb.y;
    r.z = acc.z * sc + bb.z;
    r.w = acc.w * sc + bb.w;
    if (do_relu) {
        r.x = fmaxf(r.x, 0.f); r.y = fmaxf(r.y, 0.f);
        r.z = fmaxf(r.z, 0.f); r.w = fmaxf(r.w, 0.f);
    }
    float* o = out ? out : (float*)g_x2;
    *(float4*)(o + (size_t)node * D + lane * 4) = r;
}

// ---------------------------------------------------------------------------
// Launch — kernel launches only (graph-capture safe)
// ---------------------------------------------------------------------------
extern "C" void kernel_launch(void* const* d_in, const int* in_sizes, int n_in,
                              void* d_out, int out_size) {
    const float* x  = (const float*)d_in[0];
    const int*   ei = (const int*)d_in[1];
    const float* W1 = (const float*)d_in[2];
    const float* b1 = (const float*)d_in[3];
    const float* W2 = (const float*)d_in[4];
    const float* b2 = (const float*)d_in[5];
    float* out = (float*)d_out;

    static int smem_set = 0;
    if (!smem_set) {
        cudaFuncSetAttribute(gemm_mma_kernel,
                             cudaFuncAttributeMaxDynamicSharedMemorySize,
                             GEMM_DSMEM);
        smem_set = 1;
    }

    const int T = 256;
    const int nb_n    = (NN + T - 1) / T;
    const int nb_e    = (EE + T - 1) / T;
    const int nb_gath = (NN * 32 + T - 1) / T;

    // Graph preprocessing (shared by both layers)
    detect_kernel<<<1, 32>>>(ei);
    zero_cnt_kernel<<<nb_n, T>>>();
    convert_hist_kernel<<<nb_e, T>>>(ei);
    scan1_kernel<<<SCAN_NBLK, SCAN_CHUNK>>>();
    scan2_kernel<<<1, 128>>>();
    scan3_kernel<<<nb_n, T>>>();
    fill_kernel<<<nb_e, T>>>();

    // Layer 1
    prepw_kernel<<<64, 256>>>(W1);
    gemm_mma_kernel<<<NTILES, 512, GEMM_DSMEM>>>(x);
    gather_kernel<<<nb_gath, T>>>(b1, nullptr, 1);

    // Layer 2
    prepw_kernel<<<64, 256>>>(W2);
    gemm_mma_kernel<<<NTILES, 512, GEMM_DSMEM>>>(nullptr);
    gather_kernel<<<nb_gath, T>>>(b2, out, 0);
}